// round 12
// baseline (speedup 1.0000x reference)
#include <cuda_runtime.h>
#include <cuda_bf16.h>
#include <cstdint>

#define N_NODES 100000
#define N_EDGES 1600000
#define IN_DIM  512
#define OUT_DIM 32
#define KSTEPS  10
#define ALPHA   0.1f

typedef unsigned long long ull;

// ---------------- device scratch (allocation-free) ----------------
__device__ float  g_h[N_NODES * OUT_DIM];      // 12.8 MB  (projection)
__device__ float  g_z[N_NODES * OUT_DIM];      // 12.8 MB  scaled-z ping
__device__ float  g_z2[N_NODES * OUT_DIM];     // 12.8 MB  scaled-z pong
__device__ int    g_src[N_EDGES];
__device__ int    g_dst[N_EDGES];
__device__ int    g_deg[N_NODES];
__device__ float  g_dinv[N_NODES];
__device__ int    g_rowptr[N_NODES + 1];
__device__ int    g_cursor[N_NODES];
__device__ int    g_pidx[N_EDGES];             // CSR col index (src), 4B/edge
__device__ int    g_partial[128];
__device__ int    g_is64;

__device__ __forceinline__ uint32_t smem_u32(const void* p) {
    uint32_t a;
    asm("{ .reg .u64 t; cvta.to.shared.u64 t, %1; cvt.u32.u64 %0, t; }" : "=r"(a) : "l"(p));
    return a;
}

// ---------------- init degrees + dtype sniff (fused) ----------------
__global__ void k_init_detect(const int* __restrict__ e32) {
    int i = blockIdx.x * blockDim.x + threadIdx.x;
    if (i < N_NODES) g_deg[i] = 1;   // self loop
    if (i == 0) {
        int ok = 1;
#pragma unroll
        for (int q = 1; q < 64; q += 2)
            if (e32[q] != 0) ok = 0;
        g_is64 = ok;
    }
}

// ---------------- decode edges + count in-degrees (fused) ----------------
__global__ void k_decode_count(const void* __restrict__ ei) {
    int e = blockIdx.x * blockDim.x + threadIdx.x;
    if (e >= N_EDGES) return;
    int s, d;
    if (g_is64) {
        const long long* p = (const long long*)ei;
        s = (int)p[e];
        d = (int)p[N_EDGES + e];
    } else {
        const int* p = (const int*)ei;
        s = p[e];
        d = p[N_EDGES + e];
    }
    if (s < 0) s = 0; if (s >= N_NODES) s = N_NODES - 1;
    if (d < 0) d = 0; if (d >= N_NODES) d = N_NODES - 1;
    g_src[e] = s;
    g_dst[e] = d;
    atomicAdd(&g_deg[d], 1);
}

// ---------------- dinv = rsqrt(deg) + per-block sums of (deg-1) (fused) ----------------
__global__ void k_dinv_blocksum() {
    int base = blockIdx.x * 1024;
    int t = threadIdx.x;
    int s = 0;
#pragma unroll
    for (int i = 0; i < 4; i++) {
        int idx = base + t * 4 + i;
        if (idx < N_NODES) {
            int d = g_deg[idx];
            g_dinv[idx] = rsqrtf((float)d);
            s += d - 1;
        }
    }
#pragma unroll
    for (int o = 16; o; o >>= 1) s += __shfl_down_sync(0xffffffffu, s, o);
    __shared__ int ws[8];
    if ((t & 31) == 0) ws[t >> 5] = s;
    __syncthreads();
    if (t == 0) {
        int tot = 0;
#pragma unroll
        for (int i = 0; i < 8; i++) tot += ws[i];
        g_partial[blockIdx.x] = tot;
    }
}

// ---------------- exclusive scan of block sums (1 warp) ----------------
__global__ void k_scanpartial(int nb) {
    int lane = threadIdx.x;
    int v[4];
    int tsum = 0;
#pragma unroll
    for (int i = 0; i < 4; i++) {
        int idx = lane * 4 + i;
        v[i] = (idx < nb) ? g_partial[idx] : 0;
        tsum += v[i];
    }
    int inc = tsum;
#pragma unroll
    for (int o = 1; o < 32; o <<= 1) {
        int y = __shfl_up_sync(0xffffffffu, inc, o);
        if (lane >= o) inc += y;
    }
    int run = inc - tsum;   // exclusive
#pragma unroll
    for (int i = 0; i < 4; i++) {
        int idx = lane * 4 + i;
        if (idx < nb) { g_partial[idx] = run; run += v[i]; }
    }
    int total = __shfl_sync(0xffffffffu, inc, 31);
    if (lane == 0) g_rowptr[N_NODES] = total;
}

// ---------------- full exclusive scan -> rowptr & cursor ----------------
__global__ void k_blockscan() {
    int t = threadIdx.x;
    int base = blockIdx.x * 1024 + t * 4;
    int v[4];
    int tsum = 0;
#pragma unroll
    for (int i = 0; i < 4; i++) {
        int idx = base + i;
        v[i] = (idx < N_NODES) ? (g_deg[idx] - 1) : 0;
        tsum += v[i];
    }
    int lane = t & 31, warp = t >> 5;
    int inc = tsum;
#pragma unroll
    for (int o = 1; o < 32; o <<= 1) {
        int y = __shfl_up_sync(0xffffffffu, inc, o);
        if (lane >= o) inc += y;
    }
    int excl = inc - tsum;
    __shared__ int wtot[8];
    if (lane == 31) wtot[warp] = inc;
    __syncthreads();
    if (t == 0) {
        int acc = 0;
#pragma unroll
        for (int i = 0; i < 8; i++) { int x = wtot[i]; wtot[i] = acc; acc += x; }
    }
    __syncthreads();
    int off = g_partial[blockIdx.x] + wtot[warp] + excl;
#pragma unroll
    for (int i = 0; i < 4; i++) {
        int idx = base + i;
        if (idx < N_NODES) { g_rowptr[idx] = off; g_cursor[idx] = off; off += v[i]; }
    }
}

// ---------------- dense projection via bulk-async (bypasses LDG issue floor) --------
// 148 persistent blocks (1/SM), 128 threads (4 warps). Per block:
//   W staged once as W4T[k/4][col] (float4; per-lane LDS.128 conflict-free).
//   x streamed in 32-row x 2KB contiguous chunks via cp.async.bulk into a
//   2-deep smem ping-pong (mbarrier expect_tx / parity wait), overlapped
//   with compute. Compute: lane=col, warp=8 rows; f32x2 paired over
//   (even-k, odd-k) partial sums so both operands are direct 16B loads.
__global__ __launch_bounds__(128) void k_gemm(const float* __restrict__ x,
                                              const float* __restrict__ W,
                                              const float* __restrict__ b,
                                              int rowsPerBlock) {
    extern __shared__ __align__(16) float sm[];
    float*  xs  = sm;                                   // [2][32][512]  131072 B
    float4* W4T = (float4*)(sm + 2 * 32 * IN_DIM);      // [128][32]      65536 B
    __shared__ __align__(8) unsigned long long mbar[2];

    int t = threadIdx.x, lane = t & 31, warp = t >> 5;
    int rowBase = blockIdx.x * rowsPerBlock;
    int rowEnd  = rowBase + rowsPerBlock;
    if (rowEnd > N_NODES) rowEnd = N_NODES;
    int nRows   = rowEnd - rowBase;
    int nChunks = (nRows > 0) ? ((nRows + 31) >> 5) : 0;

    // stage W -> W4T[kq][j] = W[j][4kq..4kq+3]
    for (int idx = t; idx < 4096; idx += 128) {
        int kq = idx >> 5, j = idx & 31;
        W4T[kq * 32 + j] = *(const float4*)&W[j * IN_DIM + kq * 4];
    }
    uint32_t mb0 = smem_u32(&mbar[0]);
    uint32_t mb1 = smem_u32(&mbar[1]);
    if (t == 0) {
        asm volatile("mbarrier.init.shared.b64 [%0], 1;" :: "r"(mb0));
        asm volatile("mbarrier.init.shared.b64 [%0], 1;" :: "r"(mb1));
    }
    __syncthreads();

    uint32_t xsAddr = smem_u32(xs);
    if (t == 0) {
        for (int c = 0; c < 2 && c < nChunks; c++) {
            int rows = rowEnd - (rowBase + (c << 5));
            if (rows > 32) rows = 32;
            uint32_t bytes = (uint32_t)rows << 11;
            uint32_t mb = c ? mb1 : mb0;
            asm volatile("mbarrier.arrive.expect_tx.shared.b64 _, [%0], %1;"
                         :: "r"(mb), "r"(bytes) : "memory");
            asm volatile("cp.async.bulk.shared::cta.global.mbarrier::complete_tx::bytes "
                         "[%0], [%1], %2, [%3];"
                         :: "r"(xsAddr + (uint32_t)c * 65536u),
                            "l"(x + (size_t)(rowBase + (c << 5)) * IN_DIM),
                            "r"(bytes), "r"(mb) : "memory");
        }
    }

    float bv = b[lane];

    for (int c = 0; c < nChunks; c++) {
        int buf = c & 1;
        uint32_t mb = buf ? mb1 : mb0;
        uint32_t parity = (uint32_t)((c >> 1) & 1);
        asm volatile(
            "{\n\t.reg .pred P;\n\t"
            "WL%=:\n\t"
            "mbarrier.try_wait.parity.acquire.cta.shared::cta.b64 P, [%0], %1, 0x989680;\n\t"
            "@P bra.uni WD%=;\n\t"
            "bra.uni WL%=;\n\t"
            "WD%=:\n\t}"
            :: "r"(mb), "r"(parity) : "memory");

        const float* xw = xs + buf * (32 * IN_DIM) + warp * (8 * IN_DIM);
        ull acc[8];
#pragma unroll
        for (int r = 0; r < 8; r++) acc[r] = 0ull;

#pragma unroll 2
        for (int k = 0; k < IN_DIM; k += 4) {
            ulonglong2 wv = *(const ulonglong2*)(W4T + (k >> 2) * 32 + lane);
#pragma unroll
            for (int r = 0; r < 8; r++) {
                ulonglong2 xv = *(const ulonglong2*)(xw + r * IN_DIM + k);
                asm("fma.rn.f32x2 %0, %1, %2, %0;" : "+l"(acc[r]) : "l"(xv.x), "l"(wv.x));
                asm("fma.rn.f32x2 %0, %1, %2, %0;" : "+l"(acc[r]) : "l"(xv.y), "l"(wv.y));
            }
        }

        int crow0 = rowBase + (c << 5) + warp * 8;
#pragma unroll
        for (int r = 0; r < 8; r++) {
            int row = crow0 + r;
            if (row < rowEnd) {
                float lo, hi;
                asm("mov.b64 {%0, %1}, %2;" : "=f"(lo), "=f"(hi) : "l"(acc[r]));
                float v = lo + hi + bv;
                g_h[(size_t)row * 32 + lane] = v;
                g_z[(size_t)row * 32 + lane] = g_dinv[row] * v;
            }
        }
        __syncthreads();   // buffer fully consumed by all warps

        if (t == 0 && c + 2 < nChunks) {
            asm volatile("fence.proxy.async.shared::cta;" ::: "memory");
            int c2 = c + 2;
            int rows = rowEnd - (rowBase + (c2 << 5));
            if (rows > 32) rows = 32;
            uint32_t bytes = (uint32_t)rows << 11;
            asm volatile("mbarrier.arrive.expect_tx.shared.b64 _, [%0], %1;"
                         :: "r"(mb), "r"(bytes) : "memory");
            asm volatile("cp.async.bulk.shared::cta.global.mbarrier::complete_tx::bytes "
                         "[%0], [%1], %2, [%3];"
                         :: "r"(xsAddr + (uint32_t)buf * 65536u),
                            "l"(x + (size_t)(rowBase + (c2 << 5)) * IN_DIM),
                            "r"(bytes), "r"(mb) : "memory");
        }
    }
}

// ---------------- CSR scatter (index only) ----------------
__global__ void k_scatter() {
    int e = blockIdx.x * blockDim.x + threadIdx.x;
    if (e >= N_EDGES) return;
    int s = g_src[e];
    int d = g_dst[e];
    int pos = atomicAdd(&g_cursor[d], 1);
    g_pidx[pos] = s;
}

// ---------------- propagation step (pull, warp per node, paired float2 gathers) ----
__global__ __launch_bounds__(256) void k_prop(int srcSel, int finalStep, float* __restrict__ dout) {
    int gw   = (blockIdx.x * blockDim.x + threadIdx.x) >> 5;
    int lane = threadIdx.x & 31;
    int half = lane >> 4;     // 0: row A, 1: row B
    int hl   = lane & 15;     // float2 slot within row
    const float2* zin2 = (const float2*)((srcSel == 1) ? g_z : g_z2);
    float* zoutf = finalStep ? dout : ((srcSel == 1) ? (float*)g_z2 : (float*)g_z);

    int start = g_rowptr[gw];
    int end   = g_rowptr[gw + 1];

    float ax = 0.f, ay = 0.f, bx = 0.f, by = 0.f;
    for (int base = start; base < end; base += 32) {
        int m = end - base;
        if (m > 32) m = 32;
        int si = (lane < m) ? g_pidx[base + lane] : 0;
        int kk = 0;
        for (; kk + 16 <= m; kk += 16) {
            int s[8];
#pragma unroll
            for (int p = 0; p < 8; p++)
                s[p] = __shfl_sync(0xffffffffu, si, kk + 2 * p + half);
            float2 v[8];
#pragma unroll
            for (int p = 0; p < 8; p++)
                v[p] = zin2[(size_t)s[p] * 16 + hl];
#pragma unroll
            for (int p = 0; p < 8; p += 2) {
                ax += v[p].x;     ay += v[p].y;
                bx += v[p + 1].x; by += v[p + 1].y;
            }
        }
        for (; kk < m; kk += 2) {
            int idx2 = kk + half;
            int srcl = (idx2 < m) ? idx2 : kk;
            int s = __shfl_sync(0xffffffffu, si, srcl);
            float2 v = zin2[(size_t)s * 16 + hl];
            if (idx2 < m) { ax += v.x; ay += v.y; }
        }
    }
    float sx = ax + bx, sy = ay + by;
    sx += __shfl_xor_sync(0xffffffffu, sx, 16);
    sy += __shfl_xor_sync(0xffffffffu, sy, 16);

    float di = g_dinv[gw];
    float2 zself = zin2[(size_t)gw * 16 + hl];
    float2 hv    = ((const float2*)g_h)[(size_t)gw * 16 + hl];
    float znx = (1.0f - ALPHA) * (di * (sx + zself.x)) + ALPHA * hv.x;
    float zny = (1.0f - ALPHA) * (di * (sy + zself.y)) + ALPHA * hv.y;
    if (!finalStep) { znx *= di; zny *= di; }
    if (half == 0)
        *(float2*)&zoutf[(size_t)gw * 32 + 2 * hl] = make_float2(znx, zny);
}

// ---------------- host launcher ----------------
extern "C" void kernel_launch(void* const* d_in, const int* in_sizes, int n_in,
                              void* d_out, int out_size) {
    const float* x  = (const float*)d_in[0];
    const float* W  = (const float*)d_in[1];
    const float* b  = (const float*)d_in[2];
    const void*  ei = d_in[3];
    float* out = (float*)d_out;

    const int NB = (N_NODES + 1023) / 1024;   // 98
    const int GEMM_SMEM = 2 * 32 * IN_DIM * 4 + 128 * 32 * 16;   // 196608 B
    cudaFuncSetAttribute(k_gemm, cudaFuncAttributeMaxDynamicSharedMemorySize, GEMM_SMEM);
    const int rowsPerBlock = (N_NODES + 147) / 148;              // 676

    k_init_detect<<<(N_NODES + 255) / 256, 256>>>((const int*)ei);   // 1
    k_decode_count<<<(N_EDGES + 255) / 256, 256>>>(ei);              // 2
    k_dinv_blocksum<<<NB, 256>>>();                                  // 3
    k_gemm<<<148, 128, GEMM_SMEM>>>(x, W, b, rowsPerBlock);          // 4 (ncu window)
    k_scanpartial<<<1, 32>>>(NB);                                    // 5
    k_blockscan<<<NB, 256>>>();                                      // 6
    k_scatter<<<N_EDGES / 256, 256>>>();                             // 7

    // 10 steps: zs ping-pongs g_z (srcSel=1) <-> g_z2 (srcSel=2); final writes dout.
    int srcSel = 1;
    for (int s = 1; s <= KSTEPS; s++) {
        k_prop<<<N_NODES * 32 / 256, 256>>>(srcSel, (s == KSTEPS) ? 1 : 0, out);
        srcSel = 3 - srcSel;
    }
}

// round 13
// speedup vs baseline: 1.2202x; 1.2202x over previous
#include <cuda_runtime.h>
#include <cuda_bf16.h>
#include <cstdint>

#define N_NODES 100000
#define N_EDGES 1600000
#define IN_DIM  512
#define OUT_DIM 32
#define KSTEPS  10
#define ALPHA   0.1f

typedef unsigned long long ull;

// ---------------- device scratch (allocation-free) ----------------
__device__ float  g_h[N_NODES * OUT_DIM];      // 12.8 MB  (projection)
__device__ float  g_z[N_NODES * OUT_DIM];      // 12.8 MB  scaled-z ping
__device__ float  g_z2[N_NODES * OUT_DIM];     // 12.8 MB  scaled-z pong
__device__ int    g_src[N_EDGES];
__device__ int    g_dst[N_EDGES];
__device__ int    g_deg[N_NODES];
__device__ float  g_dinv[N_NODES];
__device__ int    g_rowptr[N_NODES + 1];
__device__ int    g_cursor[N_NODES];
__device__ int    g_pidx[N_EDGES];             // CSR col index (src), 4B/edge
__device__ int    g_partial[128];
__device__ int    g_is64;

__device__ __forceinline__ uint32_t smem_u32(const void* p) {
    uint32_t a;
    asm("{ .reg .u64 t; cvta.to.shared.u64 t, %1; cvt.u32.u64 %0, t; }" : "=r"(a) : "l"(p));
    return a;
}

// ---------------- init degrees + dtype sniff (fused) ----------------
__global__ void k_init_detect(const int* __restrict__ e32) {
    int i = blockIdx.x * blockDim.x + threadIdx.x;
    if (i < N_NODES) g_deg[i] = 1;   // self loop
    if (i == 0) {
        int ok = 1;
#pragma unroll
        for (int q = 1; q < 64; q += 2)
            if (e32[q] != 0) ok = 0;
        g_is64 = ok;
    }
}

// ---------------- decode edges + count in-degrees (fused) ----------------
__global__ void k_decode_count(const void* __restrict__ ei) {
    int e = blockIdx.x * blockDim.x + threadIdx.x;
    if (e >= N_EDGES) return;
    int s, d;
    if (g_is64) {
        const long long* p = (const long long*)ei;
        s = (int)p[e];
        d = (int)p[N_EDGES + e];
    } else {
        const int* p = (const int*)ei;
        s = p[e];
        d = p[N_EDGES + e];
    }
    if (s < 0) s = 0; if (s >= N_NODES) s = N_NODES - 1;
    if (d < 0) d = 0; if (d >= N_NODES) d = N_NODES - 1;
    g_src[e] = s;
    g_dst[e] = d;
    atomicAdd(&g_deg[d], 1);
}

// ---------------- dinv = rsqrt(deg) + per-block sums of (deg-1) (fused) ----------------
__global__ void k_dinv_blocksum() {
    int base = blockIdx.x * 1024;
    int t = threadIdx.x;
    int s = 0;
#pragma unroll
    for (int i = 0; i < 4; i++) {
        int idx = base + t * 4 + i;
        if (idx < N_NODES) {
            int d = g_deg[idx];
            g_dinv[idx] = rsqrtf((float)d);
            s += d - 1;
        }
    }
#pragma unroll
    for (int o = 16; o; o >>= 1) s += __shfl_down_sync(0xffffffffu, s, o);
    __shared__ int ws[8];
    if ((t & 31) == 0) ws[t >> 5] = s;
    __syncthreads();
    if (t == 0) {
        int tot = 0;
#pragma unroll
        for (int i = 0; i < 8; i++) tot += ws[i];
        g_partial[blockIdx.x] = tot;
    }
}

// ---------------- exclusive scan of block sums (1 warp) ----------------
__global__ void k_scanpartial(int nb) {
    int lane = threadIdx.x;
    int v[4];
    int tsum = 0;
#pragma unroll
    for (int i = 0; i < 4; i++) {
        int idx = lane * 4 + i;
        v[i] = (idx < nb) ? g_partial[idx] : 0;
        tsum += v[i];
    }
    int inc = tsum;
#pragma unroll
    for (int o = 1; o < 32; o <<= 1) {
        int y = __shfl_up_sync(0xffffffffu, inc, o);
        if (lane >= o) inc += y;
    }
    int run = inc - tsum;   // exclusive
#pragma unroll
    for (int i = 0; i < 4; i++) {
        int idx = lane * 4 + i;
        if (idx < nb) { g_partial[idx] = run; run += v[i]; }
    }
    int total = __shfl_sync(0xffffffffu, inc, 31);
    if (lane == 0) g_rowptr[N_NODES] = total;
}

// ---------------- full exclusive scan -> rowptr & cursor ----------------
__global__ void k_blockscan() {
    int t = threadIdx.x;
    int base = blockIdx.x * 1024 + t * 4;
    int v[4];
    int tsum = 0;
#pragma unroll
    for (int i = 0; i < 4; i++) {
        int idx = base + i;
        v[i] = (idx < N_NODES) ? (g_deg[idx] - 1) : 0;
        tsum += v[i];
    }
    int lane = t & 31, warp = t >> 5;
    int inc = tsum;
#pragma unroll
    for (int o = 1; o < 32; o <<= 1) {
        int y = __shfl_up_sync(0xffffffffu, inc, o);
        if (lane >= o) inc += y;
    }
    int excl = inc - tsum;
    __shared__ int wtot[8];
    if (lane == 31) wtot[warp] = inc;
    __syncthreads();
    if (t == 0) {
        int acc = 0;
#pragma unroll
        for (int i = 0; i < 8; i++) { int x = wtot[i]; wtot[i] = acc; acc += x; }
    }
    __syncthreads();
    int off = g_partial[blockIdx.x] + wtot[warp] + excl;
#pragma unroll
    for (int i = 0; i < 4; i++) {
        int idx = base + i;
        if (idx < N_NODES) { g_rowptr[idx] = off; g_cursor[idx] = off; off += v[i]; }
    }
}

// ---------------- dense projection via bulk-async, 8 compute warps --------
// 148 persistent blocks (1/SM), 256 threads (8 warps). W staged once as
// W4T[k/4][col]; x streamed in 32-row x 2KB chunks via cp.async.bulk into a
// 2-deep ping-pong (mbarrier expect_tx / parity wait). Each warp computes
// 4 rows/chunk: per 4k = 1 per-lane W LDS.128 + 4 broadcast x LDS.128 +
// 8 FFMA2 (f32x2 paired over even/odd k partial sums).
__global__ __launch_bounds__(256) void k_gemm(const float* __restrict__ x,
                                              const float* __restrict__ W,
                                              const float* __restrict__ b,
                                              int rowsPerBlock) {
    extern __shared__ __align__(16) float sm[];
    float*  xs  = sm;                                   // [2][32][512]  131072 B
    float4* W4T = (float4*)(sm + 2 * 32 * IN_DIM);      // [128][32]      65536 B
    __shared__ __align__(8) unsigned long long mbar[2];

    int t = threadIdx.x, lane = t & 31, warp = t >> 5;
    int rowBase = blockIdx.x * rowsPerBlock;
    int rowEnd  = rowBase + rowsPerBlock;
    if (rowEnd > N_NODES) rowEnd = N_NODES;
    int nRows   = rowEnd - rowBase;
    int nChunks = (nRows > 0) ? ((nRows + 31) >> 5) : 0;

    // stage W -> W4T[kq][j] = W[j][4kq..4kq+3]
    for (int idx = t; idx < 4096; idx += 256) {
        int kq = idx >> 5, j = idx & 31;
        W4T[kq * 32 + j] = *(const float4*)&W[j * IN_DIM + kq * 4];
    }
    uint32_t mb0 = smem_u32(&mbar[0]);
    uint32_t mb1 = smem_u32(&mbar[1]);
    if (t == 0) {
        asm volatile("mbarrier.init.shared.b64 [%0], 1;" :: "r"(mb0));
        asm volatile("mbarrier.init.shared.b64 [%0], 1;" :: "r"(mb1));
    }
    __syncthreads();

    uint32_t xsAddr = smem_u32(xs);
    if (t == 0) {
        for (int c = 0; c < 2 && c < nChunks; c++) {
            int rows = rowEnd - (rowBase + (c << 5));
            if (rows > 32) rows = 32;
            uint32_t bytes = (uint32_t)rows << 11;
            uint32_t mb = c ? mb1 : mb0;
            asm volatile("mbarrier.arrive.expect_tx.shared.b64 _, [%0], %1;"
                         :: "r"(mb), "r"(bytes) : "memory");
            asm volatile("cp.async.bulk.shared::cta.global.mbarrier::complete_tx::bytes "
                         "[%0], [%1], %2, [%3];"
                         :: "r"(xsAddr + (uint32_t)c * 65536u),
                            "l"(x + (size_t)(rowBase + (c << 5)) * IN_DIM),
                            "r"(bytes), "r"(mb) : "memory");
        }
    }

    float bv = b[lane];

    for (int c = 0; c < nChunks; c++) {
        int buf = c & 1;
        uint32_t mb = buf ? mb1 : mb0;
        uint32_t parity = (uint32_t)((c >> 1) & 1);
        asm volatile(
            "{\n\t.reg .pred P;\n\t"
            "WL%=:\n\t"
            "mbarrier.try_wait.parity.acquire.cta.shared::cta.b64 P, [%0], %1, 0x989680;\n\t"
            "@P bra.uni WD%=;\n\t"
            "bra.uni WL%=;\n\t"
            "WD%=:\n\t}"
            :: "r"(mb), "r"(parity) : "memory");

        const float* xw = xs + buf * (32 * IN_DIM) + warp * (4 * IN_DIM);
        ull acc[4];
#pragma unroll
        for (int r = 0; r < 4; r++) acc[r] = 0ull;

#pragma unroll 4
        for (int k = 0; k < IN_DIM; k += 4) {
            ulonglong2 wv = *(const ulonglong2*)(W4T + (k >> 2) * 32 + lane);
#pragma unroll
            for (int r = 0; r < 4; r++) {
                ulonglong2 xv = *(const ulonglong2*)(xw + r * IN_DIM + k);
                asm("fma.rn.f32x2 %0, %1, %2, %0;" : "+l"(acc[r]) : "l"(xv.x), "l"(wv.x));
                asm("fma.rn.f32x2 %0, %1, %2, %0;" : "+l"(acc[r]) : "l"(xv.y), "l"(wv.y));
            }
        }

        int crow0 = rowBase + (c << 5) + warp * 4;
#pragma unroll
        for (int r = 0; r < 4; r++) {
            int row = crow0 + r;
            if (row < rowEnd) {
                float lo, hi;
                asm("mov.b64 {%0, %1}, %2;" : "=f"(lo), "=f"(hi) : "l"(acc[r]));
                float v = lo + hi + bv;
                g_h[(size_t)row * 32 + lane] = v;
                g_z[(size_t)row * 32 + lane] = g_dinv[row] * v;
            }
        }
        __syncthreads();   // buffer fully consumed by all warps

        if (t == 0 && c + 2 < nChunks) {
            asm volatile("fence.proxy.async.shared::cta;" ::: "memory");
            int c2 = c + 2;
            int rows = rowEnd - (rowBase + (c2 << 5));
            if (rows > 32) rows = 32;
            uint32_t bytes = (uint32_t)rows << 11;
            asm volatile("mbarrier.arrive.expect_tx.shared.b64 _, [%0], %1;"
                         :: "r"(mb), "r"(bytes) : "memory");
            asm volatile("cp.async.bulk.shared::cta.global.mbarrier::complete_tx::bytes "
                         "[%0], [%1], %2, [%3];"
                         :: "r"(xsAddr + (uint32_t)buf * 65536u),
                            "l"(x + (size_t)(rowBase + (c2 << 5)) * IN_DIM),
                            "r"(bytes), "r"(mb) : "memory");
        }
    }
}

// ---------------- CSR scatter (index only) ----------------
__global__ void k_scatter() {
    int e = blockIdx.x * blockDim.x + threadIdx.x;
    if (e >= N_EDGES) return;
    int s = g_src[e];
    int d = g_dst[e];
    int pos = atomicAdd(&g_cursor[d], 1);
    g_pidx[pos] = s;
}

// ---------------- propagation step (pull, warp per node, paired float2 gathers) ----
__global__ __launch_bounds__(256) void k_prop(int srcSel, int finalStep, float* __restrict__ dout) {
    int gw   = (blockIdx.x * blockDim.x + threadIdx.x) >> 5;
    int lane = threadIdx.x & 31;
    int half = lane >> 4;     // 0: row A, 1: row B
    int hl   = lane & 15;     // float2 slot within row
    const float2* zin2 = (const float2*)((srcSel == 1) ? g_z : g_z2);
    float* zoutf = finalStep ? dout : ((srcSel == 1) ? (float*)g_z2 : (float*)g_z);

    int start = g_rowptr[gw];
    int end   = g_rowptr[gw + 1];

    float ax = 0.f, ay = 0.f, bx = 0.f, by = 0.f;
    for (int base = start; base < end; base += 32) {
        int m = end - base;
        if (m > 32) m = 32;
        int si = (lane < m) ? g_pidx[base + lane] : 0;
        int kk = 0;
        for (; kk + 16 <= m; kk += 16) {
            int s[8];
#pragma unroll
            for (int p = 0; p < 8; p++)
                s[p] = __shfl_sync(0xffffffffu, si, kk + 2 * p + half);
            float2 v[8];
#pragma unroll
            for (int p = 0; p < 8; p++)
                v[p] = zin2[(size_t)s[p] * 16 + hl];
#pragma unroll
            for (int p = 0; p < 8; p += 2) {
                ax += v[p].x;     ay += v[p].y;
                bx += v[p + 1].x; by += v[p + 1].y;
            }
        }
        for (; kk < m; kk += 2) {
            int idx2 = kk + half;
            int srcl = (idx2 < m) ? idx2 : kk;
            int s = __shfl_sync(0xffffffffu, si, srcl);
            float2 v = zin2[(size_t)s * 16 + hl];
            if (idx2 < m) { ax += v.x; ay += v.y; }
        }
    }
    float sx = ax + bx, sy = ay + by;
    sx += __shfl_xor_sync(0xffffffffu, sx, 16);
    sy += __shfl_xor_sync(0xffffffffu, sy, 16);

    float di = g_dinv[gw];
    float2 zself = zin2[(size_t)gw * 16 + hl];
    float2 hv    = ((const float2*)g_h)[(size_t)gw * 16 + hl];
    float znx = (1.0f - ALPHA) * (di * (sx + zself.x)) + ALPHA * hv.x;
    float zny = (1.0f - ALPHA) * (di * (sy + zself.y)) + ALPHA * hv.y;
    if (!finalStep) { znx *= di; zny *= di; }
    if (half == 0)
        *(float2*)&zoutf[(size_t)gw * 32 + 2 * hl] = make_float2(znx, zny);
}

// ---------------- host launcher ----------------
extern "C" void kernel_launch(void* const* d_in, const int* in_sizes, int n_in,
                              void* d_out, int out_size) {
    const float* x  = (const float*)d_in[0];
    const float* W  = (const float*)d_in[1];
    const float* b  = (const float*)d_in[2];
    const void*  ei = d_in[3];
    float* out = (float*)d_out;

    const int NB = (N_NODES + 1023) / 1024;   // 98
    const int GEMM_SMEM = 2 * 32 * IN_DIM * 4 + 128 * 32 * 16;   // 196608 B
    cudaFuncSetAttribute(k_gemm, cudaFuncAttributeMaxDynamicSharedMemorySize, GEMM_SMEM);
    const int rowsPerBlock = (N_NODES + 147) / 148;              // 676

    k_init_detect<<<(N_NODES + 255) / 256, 256>>>((const int*)ei);   // 1
    k_decode_count<<<(N_EDGES + 255) / 256, 256>>>(ei);              // 2
    k_dinv_blocksum<<<NB, 256>>>();                                  // 3
    k_gemm<<<148, 256, GEMM_SMEM>>>(x, W, b, rowsPerBlock);          // 4 (ncu window)
    k_scanpartial<<<1, 32>>>(NB);                                    // 5
    k_blockscan<<<NB, 256>>>();                                      // 6
    k_scatter<<<N_EDGES / 256, 256>>>();                             // 7

    // 10 steps: zs ping-pongs g_z (srcSel=1) <-> g_z2 (srcSel=2); final writes dout.
    int srcSel = 1;
    for (int s = 1; s <= KSTEPS; s++) {
        k_prop<<<N_NODES * 32 / 256, 256>>>(srcSel, (s == KSTEPS) ? 1 : 0, out);
        srcSel = 3 - srcSel;
    }
}

// round 14
// speedup vs baseline: 1.2368x; 1.0136x over previous
#include <cuda_runtime.h>
#include <cuda_bf16.h>
#include <cstdint>

#define N_NODES 100000
#define N_EDGES 1600000
#define IN_DIM  512
#define OUT_DIM 32
#define KSTEPS  10
#define ALPHA   0.1f

typedef unsigned long long ull;

// ---------------- device scratch (allocation-free) ----------------
__device__ float  g_h[N_NODES * OUT_DIM];      // 12.8 MB  (projection)
__device__ float  g_z[N_NODES * OUT_DIM];      // 12.8 MB  scaled-z ping
__device__ float  g_z2[N_NODES * OUT_DIM];     // 12.8 MB  scaled-z pong
__device__ int    g_src[N_EDGES];
__device__ int    g_dst[N_EDGES];
__device__ int    g_deg[N_NODES];
__device__ float  g_dinv[N_NODES];
__device__ int    g_rowptr[N_NODES + 1];
__device__ int    g_cursor[N_NODES];
__device__ int    g_pidx[N_EDGES];             // CSR col index (src), 4B/edge
__device__ int    g_partial[128];
__device__ int    g_is64;

__device__ __forceinline__ uint32_t smem_u32(const void* p) {
    uint32_t a;
    asm("{ .reg .u64 t; cvta.to.shared.u64 t, %1; cvt.u32.u64 %0, t; }" : "=r"(a) : "l"(p));
    return a;
}

// ---------------- init degrees + dtype sniff (fused) ----------------
__global__ void k_init_detect(const int* __restrict__ e32) {
    int i = blockIdx.x * blockDim.x + threadIdx.x;
    if (i < N_NODES) g_deg[i] = 1;   // self loop
    if (i == 0) {
        int ok = 1;
#pragma unroll
        for (int q = 1; q < 64; q += 2)
            if (e32[q] != 0) ok = 0;
        g_is64 = ok;
    }
}

// ---------------- decode edges + count in-degrees (fused) ----------------
__global__ void k_decode_count(const void* __restrict__ ei) {
    int e = blockIdx.x * blockDim.x + threadIdx.x;
    if (e >= N_EDGES) return;
    int s, d;
    if (g_is64) {
        const long long* p = (const long long*)ei;
        s = (int)p[e];
        d = (int)p[N_EDGES + e];
    } else {
        const int* p = (const int*)ei;
        s = p[e];
        d = p[N_EDGES + e];
    }
    if (s < 0) s = 0; if (s >= N_NODES) s = N_NODES - 1;
    if (d < 0) d = 0; if (d >= N_NODES) d = N_NODES - 1;
    g_src[e] = s;
    g_dst[e] = d;
    atomicAdd(&g_deg[d], 1);
}

// ---------------- dinv = rsqrt(deg) + per-block sums of (deg-1) (fused) ----------------
__global__ void k_dinv_blocksum() {
    int base = blockIdx.x * 1024;
    int t = threadIdx.x;
    int s = 0;
#pragma unroll
    for (int i = 0; i < 4; i++) {
        int idx = base + t * 4 + i;
        if (idx < N_NODES) {
            int d = g_deg[idx];
            g_dinv[idx] = rsqrtf((float)d);
            s += d - 1;
        }
    }
#pragma unroll
    for (int o = 16; o; o >>= 1) s += __shfl_down_sync(0xffffffffu, s, o);
    __shared__ int ws[8];
    if ((t & 31) == 0) ws[t >> 5] = s;
    __syncthreads();
    if (t == 0) {
        int tot = 0;
#pragma unroll
        for (int i = 0; i < 8; i++) tot += ws[i];
        g_partial[blockIdx.x] = tot;
    }
}

// ---------------- exclusive scan of block sums (1 warp) ----------------
__global__ void k_scanpartial(int nb) {
    int lane = threadIdx.x;
    int v[4];
    int tsum = 0;
#pragma unroll
    for (int i = 0; i < 4; i++) {
        int idx = lane * 4 + i;
        v[i] = (idx < nb) ? g_partial[idx] : 0;
        tsum += v[i];
    }
    int inc = tsum;
#pragma unroll
    for (int o = 1; o < 32; o <<= 1) {
        int y = __shfl_up_sync(0xffffffffu, inc, o);
        if (lane >= o) inc += y;
    }
    int run = inc - tsum;   // exclusive
#pragma unroll
    for (int i = 0; i < 4; i++) {
        int idx = lane * 4 + i;
        if (idx < nb) { g_partial[idx] = run; run += v[i]; }
    }
    int total = __shfl_sync(0xffffffffu, inc, 31);
    if (lane == 0) g_rowptr[N_NODES] = total;
}

// ---------------- full exclusive scan -> rowptr & cursor ----------------
__global__ void k_blockscan() {
    int t = threadIdx.x;
    int base = blockIdx.x * 1024 + t * 4;
    int v[4];
    int tsum = 0;
#pragma unroll
    for (int i = 0; i < 4; i++) {
        int idx = base + i;
        v[i] = (idx < N_NODES) ? (g_deg[idx] - 1) : 0;
        tsum += v[i];
    }
    int lane = t & 31, warp = t >> 5;
    int inc = tsum;
#pragma unroll
    for (int o = 1; o < 32; o <<= 1) {
        int y = __shfl_up_sync(0xffffffffu, inc, o);
        if (lane >= o) inc += y;
    }
    int excl = inc - tsum;
    __shared__ int wtot[8];
    if (lane == 31) wtot[warp] = inc;
    __syncthreads();
    if (t == 0) {
        int acc = 0;
#pragma unroll
        for (int i = 0; i < 8; i++) { int x = wtot[i]; wtot[i] = acc; acc += x; }
    }
    __syncthreads();
    int off = g_partial[blockIdx.x] + wtot[warp] + excl;
#pragma unroll
    for (int i = 0; i < 4; i++) {
        int idx = base + i;
        if (idx < N_NODES) { g_rowptr[idx] = off; g_cursor[idx] = off; off += v[i]; }
    }
}

// ---------------- dense projection: lane=row, broadcast W, two group pipelines ----
// 148 persistent blocks, 256 threads. Warp = 32 rows x 8 cols (thread = 1 row
// x 8 cols, acc paired over even/odd k). Warps 0-3 process even chunks (buffer
// 0), warps 4-7 odd chunks (buffer 1); each group has its own mbarrier and
// named barrier, so one group's TMA overlaps the other's compute.
// Per warp per 4k: 1 per-lane x LDS.128 (row stride 516 floats -> conflict-
// free) + 8 broadcast W loads + 16 FFMA2, all operands direct 16B loads.
__global__ __launch_bounds__(256) void k_gemm(const float* __restrict__ x,
                                              const float* __restrict__ W,
                                              const float* __restrict__ b,
                                              int rowsPerBlock) {
    extern __shared__ __align__(16) float sm[];
    ull*   Wkp = (ull*)sm;            // [256 kp][32 col] pairs (W[c][2kp],W[c][2kp+1]) 65536 B
    float* xbuf = sm + 16384;         // 2 buffers x 32 rows x 516 floats = 2 x 66048 B
    __shared__ __align__(8) unsigned long long mbar[2];

    int t = threadIdx.x, lane = t & 31, warp = t >> 5;
    int g  = warp >> 2;               // group 0/1
    int cg = warp & 3;                // col group: cols 8cg..8cg+7
    int rowBase = blockIdx.x * rowsPerBlock;
    int rowEnd  = rowBase + rowsPerBlock;
    if (rowEnd > N_NODES) rowEnd = N_NODES;
    int nRows   = rowEnd - rowBase;
    int nChunks = (nRows > 0) ? ((nRows + 31) >> 5) : 0;

    // stage Wkp once
    for (int idx = t; idx < 8192; idx += 256) {
        int kp = idx >> 5, c = idx & 31;
        Wkp[kp * 32 + c] = *(const ull*)(W + c * IN_DIM + 2 * kp);
    }
    if (t < 2) {
        uint32_t m = smem_u32(&mbar[t]);
        asm volatile("mbarrier.init.shared.b64 [%0], 1;" :: "r"(m));
    }
    __syncthreads();

    uint32_t mb = smem_u32(&mbar[g]);
    uint32_t xaddr = smem_u32(xbuf + g * 16512);
    const float* xr = xbuf + g * 16512 + lane * 516;
    float4 bv0 = *(const float4*)&b[8 * cg];
    float4 bv1 = *(const float4*)&b[8 * cg + 4];
    int tg = t & 127;
    int it = 0;

    for (int c = g; c < nChunks; c += 2, it++) {
        int r0 = rowBase + (c << 5);
        int rows = rowEnd - r0;
        if (rows > 32) rows = 32;

        if (tg == 0) {
            asm volatile("fence.proxy.async.shared::cta;" ::: "memory");
            uint32_t bytes = (uint32_t)rows << 11;
            asm volatile("mbarrier.arrive.expect_tx.shared.b64 _, [%0], %1;"
                         :: "r"(mb), "r"(bytes) : "memory");
            for (int r = 0; r < rows; r++) {
                asm volatile("cp.async.bulk.shared::cta.global.mbarrier::complete_tx::bytes "
                             "[%0], [%1], %2, [%3];"
                             :: "r"(xaddr + (uint32_t)r * 2064u),
                                "l"(x + (size_t)(r0 + r) * IN_DIM),
                                "n"(2048), "r"(mb) : "memory");
            }
        }
        {
            uint32_t parity = (uint32_t)(it & 1);
            asm volatile(
                "{\n\t.reg .pred P;\n\t"
                "WL%=:\n\t"
                "mbarrier.try_wait.parity.acquire.cta.shared::cta.b64 P, [%0], %1, 0x989680;\n\t"
                "@P bra.uni WD%=;\n\t"
                "bra.uni WL%=;\n\t"
                "WD%=:\n\t}"
                :: "r"(mb), "r"(parity) : "memory");
        }

        ull acc0 = 0, acc1 = 0, acc2 = 0, acc3 = 0, acc4 = 0, acc5 = 0, acc6 = 0, acc7 = 0;
#pragma unroll 4
        for (int q = 0; q < 128; q++) {            // q = 4k step: k = 4q
            ulonglong2 xv = *(const ulonglong2*)(xr + 4 * q);   // (k,k+1),(k+2,k+3)
            const ull* wp0 = Wkp + (ull)(2 * q) * 32 + 8 * cg;      // kp = 2q
            const ull* wp1 = wp0 + 32;                               // kp = 2q+1
            ulonglong2 wa = *(const ulonglong2*)(wp0);
            ulonglong2 wb = *(const ulonglong2*)(wp0 + 2);
            ulonglong2 wc = *(const ulonglong2*)(wp0 + 4);
            ulonglong2 wd = *(const ulonglong2*)(wp0 + 6);
            asm("fma.rn.f32x2 %0, %1, %2, %0;" : "+l"(acc0) : "l"(xv.x), "l"(wa.x));
            asm("fma.rn.f32x2 %0, %1, %2, %0;" : "+l"(acc1) : "l"(xv.x), "l"(wa.y));
            asm("fma.rn.f32x2 %0, %1, %2, %0;" : "+l"(acc2) : "l"(xv.x), "l"(wb.x));
            asm("fma.rn.f32x2 %0, %1, %2, %0;" : "+l"(acc3) : "l"(xv.x), "l"(wb.y));
            asm("fma.rn.f32x2 %0, %1, %2, %0;" : "+l"(acc4) : "l"(xv.x), "l"(wc.x));
            asm("fma.rn.f32x2 %0, %1, %2, %0;" : "+l"(acc5) : "l"(xv.x), "l"(wc.y));
            asm("fma.rn.f32x2 %0, %1, %2, %0;" : "+l"(acc6) : "l"(xv.x), "l"(wd.x));
            asm("fma.rn.f32x2 %0, %1, %2, %0;" : "+l"(acc7) : "l"(xv.x), "l"(wd.y));
            ulonglong2 wa1 = *(const ulonglong2*)(wp1);
            ulonglong2 wb1 = *(const ulonglong2*)(wp1 + 2);
            ulonglong2 wc1 = *(const ulonglong2*)(wp1 + 4);
            ulonglong2 wd1 = *(const ulonglong2*)(wp1 + 6);
            asm("fma.rn.f32x2 %0, %1, %2, %0;" : "+l"(acc0) : "l"(xv.y), "l"(wa1.x));
            asm("fma.rn.f32x2 %0, %1, %2, %0;" : "+l"(acc1) : "l"(xv.y), "l"(wa1.y));
            asm("fma.rn.f32x2 %0, %1, %2, %0;" : "+l"(acc2) : "l"(xv.y), "l"(wb1.x));
            asm("fma.rn.f32x2 %0, %1, %2, %0;" : "+l"(acc3) : "l"(xv.y), "l"(wb1.y));
            asm("fma.rn.f32x2 %0, %1, %2, %0;" : "+l"(acc4) : "l"(xv.y), "l"(wc1.x));
            asm("fma.rn.f32x2 %0, %1, %2, %0;" : "+l"(acc5) : "l"(xv.y), "l"(wc1.y));
            asm("fma.rn.f32x2 %0, %1, %2, %0;" : "+l"(acc6) : "l"(xv.y), "l"(wd1.x));
            asm("fma.rn.f32x2 %0, %1, %2, %0;" : "+l"(acc7) : "l"(xv.y), "l"(wd1.y));
        }

        int row = r0 + lane;
        if (lane < rows) {
            float v[8];
            ull accs[8] = {acc0, acc1, acc2, acc3, acc4, acc5, acc6, acc7};
#pragma unroll
            for (int j = 0; j < 8; j++) {
                float e, o;
                asm("mov.b64 {%0, %1}, %2;" : "=f"(e), "=f"(o) : "l"(accs[j]));
                v[j] = e + o;
            }
            float4 h0 = make_float4(v[0] + bv0.x, v[1] + bv0.y, v[2] + bv0.z, v[3] + bv0.w);
            float4 h1 = make_float4(v[4] + bv1.x, v[5] + bv1.y, v[6] + bv1.z, v[7] + bv1.w);
            *(float4*)&g_h[(size_t)row * 32 + 8 * cg]     = h0;
            *(float4*)&g_h[(size_t)row * 32 + 8 * cg + 4] = h1;
            float di = g_dinv[row];
            *(float4*)&g_z[(size_t)row * 32 + 8 * cg] =
                make_float4(h0.x * di, h0.y * di, h0.z * di, h0.w * di);
            *(float4*)&g_z[(size_t)row * 32 + 8 * cg + 4] =
                make_float4(h1.x * di, h1.y * di, h1.z * di, h1.w * di);
        }
        // group barrier: all 4 warps of this group done with the buffer
        asm volatile("bar.sync %0, 128;" :: "r"(g + 1) : "memory");
    }
}

// ---------------- CSR scatter (index only) ----------------
__global__ void k_scatter() {
    int e = blockIdx.x * blockDim.x + threadIdx.x;
    if (e >= N_EDGES) return;
    int s = g_src[e];
    int d = g_dst[e];
    int pos = atomicAdd(&g_cursor[d], 1);
    g_pidx[pos] = s;
}

// ---------------- propagation step (pull, warp per node, paired float2 gathers) ----
__global__ __launch_bounds__(256) void k_prop(int srcSel, int finalStep, float* __restrict__ dout) {
    int gw   = (blockIdx.x * blockDim.x + threadIdx.x) >> 5;
    int lane = threadIdx.x & 31;
    int half = lane >> 4;     // 0: row A, 1: row B
    int hl   = lane & 15;     // float2 slot within row
    const float2* zin2 = (const float2*)((srcSel == 1) ? g_z : g_z2);
    float* zoutf = finalStep ? dout : ((srcSel == 1) ? (float*)g_z2 : (float*)g_z);

    int start = g_rowptr[gw];
    int end   = g_rowptr[gw + 1];

    float ax = 0.f, ay = 0.f, bx = 0.f, by = 0.f;
    for (int base = start; base < end; base += 32) {
        int m = end - base;
        if (m > 32) m = 32;
        int si = (lane < m) ? g_pidx[base + lane] : 0;
        int kk = 0;
        for (; kk + 16 <= m; kk += 16) {
            int s[8];
#pragma unroll
            for (int p = 0; p < 8; p++)
                s[p] = __shfl_sync(0xffffffffu, si, kk + 2 * p + half);
            float2 v[8];
#pragma unroll
            for (int p = 0; p < 8; p++)
                v[p] = zin2[(size_t)s[p] * 16 + hl];
#pragma unroll
            for (int p = 0; p < 8; p += 2) {
                ax += v[p].x;     ay += v[p].y;
                bx += v[p + 1].x; by += v[p + 1].y;
            }
        }
        for (; kk < m; kk += 2) {
            int idx2 = kk + half;
            int srcl = (idx2 < m) ? idx2 : kk;
            int s = __shfl_sync(0xffffffffu, si, srcl);
            float2 v = zin2[(size_t)s * 16 + hl];
            if (idx2 < m) { ax += v.x; ay += v.y; }
        }
    }
    float sx = ax + bx, sy = ay + by;
    sx += __shfl_xor_sync(0xffffffffu, sx, 16);
    sy += __shfl_xor_sync(0xffffffffu, sy, 16);

    float di = g_dinv[gw];
    float2 zself = zin2[(size_t)gw * 16 + hl];
    float2 hv    = ((const float2*)g_h)[(size_t)gw * 16 + hl];
    float znx = (1.0f - ALPHA) * (di * (sx + zself.x)) + ALPHA * hv.x;
    float zny = (1.0f - ALPHA) * (di * (sy + zself.y)) + ALPHA * hv.y;
    if (!finalStep) { znx *= di; zny *= di; }
    if (half == 0)
        *(float2*)&zoutf[(size_t)gw * 32 + 2 * hl] = make_float2(znx, zny);
}

// ---------------- host launcher ----------------
extern "C" void kernel_launch(void* const* d_in, const int* in_sizes, int n_in,
                              void* d_out, int out_size) {
    const float* x  = (const float*)d_in[0];
    const float* W  = (const float*)d_in[1];
    const float* b  = (const float*)d_in[2];
    const void*  ei = d_in[3];
    float* out = (float*)d_out;

    const int NB = (N_NODES + 1023) / 1024;   // 98
    const int GEMM_SMEM = 65536 + 2 * 66048;  // 197632 B
    cudaFuncSetAttribute(k_gemm, cudaFuncAttributeMaxDynamicSharedMemorySize, GEMM_SMEM);
    const int rowsPerBlock = (N_NODES + 147) / 148;              // 676

    k_init_detect<<<(N_NODES + 255) / 256, 256>>>((const int*)ei);   // 1
    k_decode_count<<<(N_EDGES + 255) / 256, 256>>>(ei);              // 2
    k_dinv_blocksum<<<NB, 256>>>();                                  // 3
    k_gemm<<<148, 256, GEMM_SMEM>>>(x, W, b, rowsPerBlock);          // 4 (ncu window)
    k_scanpartial<<<1, 32>>>(NB);                                    // 5
    k_blockscan<<<NB, 256>>>();                                      // 6
    k_scatter<<<N_EDGES / 256, 256>>>();                             // 7

    // 10 steps: zs ping-pongs g_z (srcSel=1) <-> g_z2 (srcSel=2); final writes dout.
    int srcSel = 1;
    for (int s = 1; s <= KSTEPS; s++) {
        k_prop<<<N_NODES * 32 / 256, 256>>>(srcSel, (s == KSTEPS) ? 1 : 0, out);
        srcSel = 3 - srcSel;
    }
}